// round 2
// baseline (speedup 1.0000x reference)
#include <cuda_runtime.h>

#define BATCH 8
#define CH 256
#define HH 56
#define WW 56
#define HWSZ 3136     // 56*56
#define NPIX 25088    // BATCH*HWSZ, == 196*128 exactly
#define EPSBN 1e-5f

// ---------------- scratch (device globals; no allocations allowed) -----------
static __device__ float g_xt[NPIX * CH];        // x in NHWC
static __device__ float g_out1[NPIX * CH];      // relu(bn1(conv1(x))) in NHWC
static __device__ float g_offs[NPIX * 18];      // offsets, [pix][18]
static __device__ float g_w1t[9 * CH * CH];     // conv1_w as [k][c][oc]
static __device__ float g_w2t[9 * CH * CH];     // conv2_w as [k][c][oc]
static __device__ float g_wofft[9 * CH * 32];   // off_w as [k][c][oc], oc padded 18->32 with zeros

// ---------------- NCHW -> NHWC transpose of x --------------------------------
__global__ void nchw_to_nhwc(const float* __restrict__ x) {
    __shared__ float tile[32][33];
    const int b   = blockIdx.z;
    const int hw0 = blockIdx.x * 32;
    const int c0  = blockIdx.y * 32;
    const int tx = threadIdx.x, ty = threadIdx.y;
#pragma unroll
    for (int j = 0; j < 4; ++j)
        tile[ty + j * 8][tx] = x[(b * CH + c0 + ty + j * 8) * HWSZ + hw0 + tx];
    __syncthreads();
#pragma unroll
    for (int j = 0; j < 4; ++j)
        g_xt[(b * HWSZ + hw0 + ty + j * 8) * CH + c0 + tx] = tile[tx][ty + j * 8];
}

// ---------------- weight transposes OIHW -> [k][c][oc] -----------------------
__global__ void transpose_w_big(const float* __restrict__ w, int which) {
    const int idx = blockIdx.x * 256 + threadIdx.x;   // over [9][256][256]
    const int k  = idx / (CH * CH);
    const int r  = idx - k * CH * CH;
    const int c  = r >> 8;
    const int oc = r & 255;
    const float val = w[(oc * CH + c) * 9 + k];
    if (which) g_w2t[idx] = val; else g_w1t[idx] = val;
}

__global__ void transpose_w_off(const float* __restrict__ w) {
    const int idx = blockIdx.x * 256 + threadIdx.x;   // over [9][256][32]
    const int k  = idx / (CH * 32);
    const int r  = idx - k * CH * 32;
    const int c  = r >> 5;
    const int oc = r & 31;
    g_wofft[idx] = (oc < 18) ? w[(oc * CH + c) * 9 + k] : 0.f;
}

// ---------------- conv1 (3x3, 256->256) + BN1 + ReLU, NHWC -> NHWC -----------
// BM=128 pixels, BN=128 out-channels, BK=16, 256 threads, 8x8 register tile.
__global__ __launch_bounds__(256, 2)
void conv1_bnrelu(const float* __restrict__ bg, const float* __restrict__ bbeta,
                  const float* __restrict__ bm, const float* __restrict__ bv) {
    __shared__ float As[16][132];
    __shared__ float Bs[16][132];
    const int tid     = threadIdx.x;
    const int pixbase = blockIdx.x * 128;
    const int octile  = blockIdx.y * 128;

    // A loader: 512 float4 per slice; thread handles f=tid and f=tid+256
    const int pA0 = tid >> 2;              // pixel 0..63 (and +64)
    const int cA  = (tid & 3) << 2;        // channel-within-slice 0,4,8,12
    const int gp0 = pixbase + pA0;
    const int gp1 = gp0 + 64;
    const int b0 = gp0 / HWSZ; const int r0 = gp0 - b0 * HWSZ;
    const int b1 = gp1 / HWSZ; const int r1 = gp1 - b1 * HWSZ;
    const int py0 = r0 / WW, px0 = r0 - (r0 / WW) * WW;
    const int py1 = r1 / WW, px1 = r1 - (r1 / WW) * WW;

    // B loader
    const int ccB = tid >> 5;              // 0..7 (and +8)
    const int ocB = (tid & 31) << 2;       // 0..124

    // compute mapping
    const int txc = tid & 15, tyc = tid >> 4;
    const int o0 = txc << 3, p0 = tyc << 3;

    float acc[8][8];
#pragma unroll
    for (int i = 0; i < 8; ++i)
#pragma unroll
        for (int j = 0; j < 8; ++j) acc[i][j] = 0.f;

    for (int k = 0; k < 9; ++k) {
        const int ky = k / 3, kx = k - (k / 3) * 3;
        const int sy0 = py0 + ky - 1, sx0 = px0 + kx - 1;
        const int sy1 = py1 + ky - 1, sx1 = px1 + kx - 1;
        const bool v0 = ((unsigned)sy0 < HH) & ((unsigned)sx0 < WW);
        const bool v1 = ((unsigned)sy1 < HH) & ((unsigned)sx1 < WW);
        const float* pa0 = g_xt + ((b0 * HWSZ + sy0 * WW + sx0) << 8) + cA;
        const float* pa1 = g_xt + ((b1 * HWSZ + sy1 * WW + sx1) << 8) + cA;
        const float* pw  = g_w1t + ((k * CH + ccB) << 8) + octile + ocB;

        for (int c0 = 0; c0 < CH; c0 += 16) {
            float4 a0 = make_float4(0.f, 0.f, 0.f, 0.f);
            float4 a1 = make_float4(0.f, 0.f, 0.f, 0.f);
            if (v0) a0 = *(const float4*)(pa0 + c0);
            if (v1) a1 = *(const float4*)(pa1 + c0);
            const float4 w0 = *(const float4*)(pw + (c0 << 8));
            const float4 w1 = *(const float4*)(pw + ((c0 + 8) << 8));
            __syncthreads();
            As[cA + 0][pA0] = a0.x; As[cA + 1][pA0] = a0.y;
            As[cA + 2][pA0] = a0.z; As[cA + 3][pA0] = a0.w;
            As[cA + 0][pA0 + 64] = a1.x; As[cA + 1][pA0 + 64] = a1.y;
            As[cA + 2][pA0 + 64] = a1.z; As[cA + 3][pA0 + 64] = a1.w;
            *(float4*)&Bs[ccB][ocB]     = w0;
            *(float4*)&Bs[ccB + 8][ocB] = w1;
            __syncthreads();
#pragma unroll
            for (int cc = 0; cc < 16; ++cc) {
                const float4 alo = *(const float4*)&As[cc][p0];
                const float4 ahi = *(const float4*)&As[cc][p0 + 4];
                const float4 blo = *(const float4*)&Bs[cc][o0];
                const float4 bhi = *(const float4*)&Bs[cc][o0 + 4];
                const float a[8]  = {alo.x, alo.y, alo.z, alo.w, ahi.x, ahi.y, ahi.z, ahi.w};
                const float bb[8] = {blo.x, blo.y, blo.z, blo.w, bhi.x, bhi.y, bhi.z, bhi.w};
#pragma unroll
                for (int i = 0; i < 8; ++i)
#pragma unroll
                    for (int j = 0; j < 8; ++j)
                        acc[i][j] = fmaf(a[i], bb[j], acc[i][j]);
            }
        }
    }

    float inv[8], bet[8];
#pragma unroll
    for (int j = 0; j < 8; ++j) {
        const int oc = octile + o0 + j;
        const float iv = bg[oc] * rsqrtf(bv[oc] + EPSBN);
        inv[j] = iv;
        bet[j] = bbeta[oc] - bm[oc] * iv;
    }
#pragma unroll
    for (int i = 0; i < 8; ++i) {
        const int gp = pixbase + p0 + i;
        float4 lo, hi;
        lo.x = fmaxf(fmaf(acc[i][0], inv[0], bet[0]), 0.f);
        lo.y = fmaxf(fmaf(acc[i][1], inv[1], bet[1]), 0.f);
        lo.z = fmaxf(fmaf(acc[i][2], inv[2], bet[2]), 0.f);
        lo.w = fmaxf(fmaf(acc[i][3], inv[3], bet[3]), 0.f);
        hi.x = fmaxf(fmaf(acc[i][4], inv[4], bet[4]), 0.f);
        hi.y = fmaxf(fmaf(acc[i][5], inv[5], bet[5]), 0.f);
        hi.z = fmaxf(fmaf(acc[i][6], inv[6], bet[6]), 0.f);
        hi.w = fmaxf(fmaf(acc[i][7], inv[7], bet[7]), 0.f);
        *(float4*)&g_out1[gp * CH + octile + o0]     = lo;
        *(float4*)&g_out1[gp * CH + octile + o0 + 4] = hi;
    }
}

// ---------------- offset conv (3x3, 256->18 padded to 32) --------------------
// BM=128 pixels, BN=32 (padded), BK=16, 256 threads, 8x2 tile.
__global__ __launch_bounds__(256, 2)
void conv_off(const float* __restrict__ offb) {
    __shared__ float As[16][132];
    __shared__ float Bs[16][36];
    const int tid     = threadIdx.x;
    const int pixbase = blockIdx.x * 128;

    const int pA0 = tid >> 2;
    const int cA  = (tid & 3) << 2;
    const int gp0 = pixbase + pA0;
    const int gp1 = gp0 + 64;
    const int b0 = gp0 / HWSZ; const int r0 = gp0 - b0 * HWSZ;
    const int b1 = gp1 / HWSZ; const int r1 = gp1 - b1 * HWSZ;
    const int py0 = r0 / WW, px0 = r0 - (r0 / WW) * WW;
    const int py1 = r1 / WW, px1 = r1 - (r1 / WW) * WW;

    const int ccB = tid >> 3;          // valid when tid<128: 0..15
    const int ocB = (tid & 7) << 2;    // 0..28

    const int txc = tid & 15, tyc = tid >> 4;
    const int o0 = txc << 1, p0 = tyc << 3;

    float acc[8][2];
#pragma unroll
    for (int i = 0; i < 8; ++i) { acc[i][0] = 0.f; acc[i][1] = 0.f; }

    for (int k = 0; k < 9; ++k) {
        const int ky = k / 3, kx = k - (k / 3) * 3;
        const int sy0 = py0 + ky - 1, sx0 = px0 + kx - 1;
        const int sy1 = py1 + ky - 1, sx1 = px1 + kx - 1;
        const bool v0 = ((unsigned)sy0 < HH) & ((unsigned)sx0 < WW);
        const bool v1 = ((unsigned)sy1 < HH) & ((unsigned)sx1 < WW);
        const float* pa0 = g_out1 + ((b0 * HWSZ + sy0 * WW + sx0) << 8) + cA;
        const float* pa1 = g_out1 + ((b1 * HWSZ + sy1 * WW + sx1) << 8) + cA;

        for (int c0 = 0; c0 < CH; c0 += 16) {
            float4 a0 = make_float4(0.f, 0.f, 0.f, 0.f);
            float4 a1 = make_float4(0.f, 0.f, 0.f, 0.f);
            if (v0) a0 = *(const float4*)(pa0 + c0);
            if (v1) a1 = *(const float4*)(pa1 + c0);
            float4 wv = make_float4(0.f, 0.f, 0.f, 0.f);
            if (tid < 128) wv = *(const float4*)(g_wofft + (k * CH + c0 + ccB) * 32 + ocB);
            __syncthreads();
            As[cA + 0][pA0] = a0.x; As[cA + 1][pA0] = a0.y;
            As[cA + 2][pA0] = a0.z; As[cA + 3][pA0] = a0.w;
            As[cA + 0][pA0 + 64] = a1.x; As[cA + 1][pA0 + 64] = a1.y;
            As[cA + 2][pA0 + 64] = a1.z; As[cA + 3][pA0 + 64] = a1.w;
            if (tid < 128) *(float4*)&Bs[ccB][ocB] = wv;
            __syncthreads();
#pragma unroll
            for (int cc = 0; cc < 16; ++cc) {
                const float4 alo = *(const float4*)&As[cc][p0];
                const float4 ahi = *(const float4*)&As[cc][p0 + 4];
                const float2 bv2 = *(const float2*)&Bs[cc][o0];
                const float a[8] = {alo.x, alo.y, alo.z, alo.w, ahi.x, ahi.y, ahi.z, ahi.w};
#pragma unroll
                for (int i = 0; i < 8; ++i) {
                    acc[i][0] = fmaf(a[i], bv2.x, acc[i][0]);
                    acc[i][1] = fmaf(a[i], bv2.y, acc[i][1]);
                }
            }
        }
    }

    if (o0 < 18) {
        const float bo0 = offb[o0], bo1 = offb[o0 + 1];
#pragma unroll
        for (int i = 0; i < 8; ++i) {
            const int gp = pixbase + p0 + i;
            g_offs[gp * 18 + o0]     = acc[i][0] + bo0;
            g_offs[gp * 18 + o0 + 1] = acc[i][1] + bo1;
        }
    }
}

// ---------------- deformable conv + BN2 + residual + ReLU --------------------
__global__ __launch_bounds__(256, 2)
void deform_bnrelu(const float* __restrict__ bg, const float* __restrict__ bbeta,
                   const float* __restrict__ bm, const float* __restrict__ bv,
                   const float* __restrict__ resid, float* __restrict__ out) {
    __shared__ float As[16][132];
    __shared__ float Bs[16][132];
    __shared__ float4 cw[128 * 9];   // bilinear corner weights (validity-masked)
    __shared__ int   cpk[128 * 9];   // packed clamped corner coords

    const int tid     = threadIdx.x;
    const int pixbase = blockIdx.x * 128;
    const int octile  = blockIdx.y * 128;

    // Precompute sampling coords/weights for all (pixel, tap) of this block.
    for (int idx = tid; idx < 128 * 9; idx += 256) {
        const int p = idx / 9, k = idx - (idx / 9) * 9;
        const int gp = pixbase + p;
        const int b = gp / HWSZ; const int rem = gp - b * HWSZ;
        const int yy = rem / WW; const int xx = rem - yy * WW;
        const float oy = g_offs[gp * 18 + k];
        const float ox = g_offs[gp * 18 + 9 + k];
        const float ys = (float)(yy + k / 3 - 1) + oy;
        const float xs = (float)(xx + (k - (k / 3) * 3) - 1) + ox;
        const float yf = floorf(ys), xf = floorf(xs);
        const float ty = ys - yf, tx = xs - xf;
        const int iy0 = (int)yf, ix0 = (int)xf;
        const int iy1 = iy0 + 1, ix1 = ix0 + 1;
        const float vy0 = ((unsigned)iy0 < HH) ? 1.f : 0.f;
        const float vy1 = ((unsigned)iy1 < HH) ? 1.f : 0.f;
        const float vx0 = ((unsigned)ix0 < WW) ? 1.f : 0.f;
        const float vx1 = ((unsigned)ix1 < WW) ? 1.f : 0.f;
        cw[idx] = make_float4((1.f - ty) * (1.f - tx) * vy0 * vx0,
                              (1.f - ty) * tx         * vy0 * vx1,
                              ty         * (1.f - tx) * vy1 * vx0,
                              ty         * tx         * vy1 * vx1);
        const int cy0 = min(max(iy0, 0), HH - 1), cy1 = min(max(iy1, 0), HH - 1);
        const int cx0 = min(max(ix0, 0), WW - 1), cx1 = min(max(ix1, 0), WW - 1);
        cpk[idx] = cy0 | (cx0 << 8) | (cy1 << 16) | (cx1 << 24);
    }
    __syncthreads();

    const int pA0 = tid >> 2;
    const int cA  = (tid & 3) << 2;
    const int gp0 = pixbase + pA0, gp1 = gp0 + 64;
    const int bb0 = (gp0 / HWSZ) * HWSZ;
    const int bb1 = (gp1 / HWSZ) * HWSZ;
    const int ccB = tid >> 5;
    const int ocB = (tid & 31) << 2;
    const int txc = tid & 15, tyc = tid >> 4;
    const int o0 = txc << 3, p0 = tyc << 3;
    const float* gin = g_out1 + cA;

    float acc[8][8];
#pragma unroll
    for (int i = 0; i < 8; ++i)
#pragma unroll
        for (int j = 0; j < 8; ++j) acc[i][j] = 0.f;

    for (int k = 0; k < 9; ++k) {
        const float4 wA0 = cw[pA0 * 9 + k];
        const int    pk0 = cpk[pA0 * 9 + k];
        const float4 wA1 = cw[(pA0 + 64) * 9 + k];
        const int    pk1 = cpk[(pA0 + 64) * 9 + k];
        const int b00_0 = (bb0 + (pk0 & 255) * WW + ((pk0 >> 8) & 255)) << 8;
        const int b01_0 = (bb0 + (pk0 & 255) * WW + ((pk0 >> 24) & 255)) << 8;
        const int b10_0 = (bb0 + ((pk0 >> 16) & 255) * WW + ((pk0 >> 8) & 255)) << 8;
        const int b11_0 = (bb0 + ((pk0 >> 16) & 255) * WW + ((pk0 >> 24) & 255)) << 8;
        const int b00_1 = (bb1 + (pk1 & 255) * WW + ((pk1 >> 8) & 255)) << 8;
        const int b01_1 = (bb1 + (pk1 & 255) * WW + ((pk1 >> 24) & 255)) << 8;
        const int b10_1 = (bb1 + ((pk1 >> 16) & 255) * WW + ((pk1 >> 8) & 255)) << 8;
        const int b11_1 = (bb1 + ((pk1 >> 16) & 255) * WW + ((pk1 >> 24) & 255)) << 8;
        const float* pw = g_w2t + ((k * CH + ccB) << 8) + octile + ocB;

        for (int c0 = 0; c0 < CH; c0 += 16) {
            const float4 s00 = *(const float4*)(gin + b00_0 + c0);
            const float4 s01 = *(const float4*)(gin + b01_0 + c0);
            const float4 s10 = *(const float4*)(gin + b10_0 + c0);
            const float4 s11 = *(const float4*)(gin + b11_0 + c0);
            float4 a0;
            a0.x = fmaf(wA0.x, s00.x, fmaf(wA0.y, s01.x, fmaf(wA0.z, s10.x, wA0.w * s11.x)));
            a0.y = fmaf(wA0.x, s00.y, fmaf(wA0.y, s01.y, fmaf(wA0.z, s10.y, wA0.w * s11.y)));
            a0.z = fmaf(wA0.x, s00.z, fmaf(wA0.y, s01.z, fmaf(wA0.z, s10.z, wA0.w * s11.z)));
            a0.w = fmaf(wA0.x, s00.w, fmaf(wA0.y, s01.w, fmaf(wA0.z, s10.w, wA0.w * s11.w)));
            const float4 t00 = *(const float4*)(gin + b00_1 + c0);
            const float4 t01 = *(const float4*)(gin + b01_1 + c0);
            const float4 t10 = *(const float4*)(gin + b10_1 + c0);
            const float4 t11 = *(const float4*)(gin + b11_1 + c0);
            float4 a1;
            a1.x = fmaf(wA1.x, t00.x, fmaf(wA1.y, t01.x, fmaf(wA1.z, t10.x, wA1.w * t11.x)));
            a1.y = fmaf(wA1.x, t00.y, fmaf(wA1.y, t01.y, fmaf(wA1.z, t10.y, wA1.w * t11.y)));
            a1.z = fmaf(wA1.x, t00.z, fmaf(wA1.y, t01.z, fmaf(wA1.z, t10.z, wA1.w * t11.z)));
            a1.w = fmaf(wA1.x, t00.w, fmaf(wA1.y, t01.w, fmaf(wA1.z, t10.w, wA1.w * t11.w)));
            const float4 w0 = *(const float4*)(pw + (c0 << 8));
            const float4 w1 = *(const float4*)(pw + ((c0 + 8) << 8));
            __syncthreads();
            As[cA + 0][pA0] = a0.x; As[cA + 1][pA0] = a0.y;
            As[cA + 2][pA0] = a0.z; As[cA + 3][pA0] = a0.w;
            As[cA + 0][pA0 + 64] = a1.x; As[cA + 1][pA0 + 64] = a1.y;
            As[cA + 2][pA0 + 64] = a1.z; As[cA + 3][pA0 + 64] = a1.w;
            *(float4*)&Bs[ccB][ocB]     = w0;
            *(float4*)&Bs[ccB + 8][ocB] = w1;
            __syncthreads();
#pragma unroll
            for (int cc = 0; cc < 16; ++cc) {
                const float4 alo = *(const float4*)&As[cc][p0];
                const float4 ahi = *(const float4*)&As[cc][p0 + 4];
                const float4 blo = *(const float4*)&Bs[cc][o0];
                const float4 bhi = *(const float4*)&Bs[cc][o0 + 4];
                const float a[8]  = {alo.x, alo.y, alo.z, alo.w, ahi.x, ahi.y, ahi.z, ahi.w};
                const float bb[8] = {blo.x, blo.y, blo.z, blo.w, bhi.x, bhi.y, bhi.z, bhi.w};
#pragma unroll
                for (int i = 0; i < 8; ++i)
#pragma unroll
                    for (int j = 0; j < 8; ++j)
                        acc[i][j] = fmaf(a[i], bb[j], acc[i][j]);
            }
        }
    }

    float inv[8], bet[8];
#pragma unroll
    for (int j = 0; j < 8; ++j) {
        const int oc = octile + o0 + j;
        const float iv = bg[oc] * rsqrtf(bv[oc] + EPSBN);
        inv[j] = iv;
        bet[j] = bbeta[oc] - bm[oc] * iv;
    }
#pragma unroll
    for (int i = 0; i < 8; ++i) {
        const int gp = pixbase + p0 + i;
        const int b = gp / HWSZ; const int rem = gp - b * HWSZ;
        const int base = b * (CH * HWSZ) + rem;
#pragma unroll
        for (int j = 0; j < 8; ++j) {
            const int addr = base + (octile + o0 + j) * HWSZ;
            out[addr] = fmaxf(fmaf(acc[i][j], inv[j], bet[j]) + resid[addr], 0.f);
        }
    }
}

// ---------------- launch ------------------------------------------------------
extern "C" void kernel_launch(void* const* d_in, const int* in_sizes, int n_in,
                              void* d_out, int out_size) {
    const float* x    = (const float*)d_in[0];
    const float* w1   = (const float*)d_in[1];
    const float* bn1g = (const float*)d_in[2];
    const float* bn1b = (const float*)d_in[3];
    const float* bn1m = (const float*)d_in[4];
    const float* bn1v = (const float*)d_in[5];
    const float* woff = (const float*)d_in[6];
    const float* offb = (const float*)d_in[7];
    const float* w2   = (const float*)d_in[8];
    const float* bn2g = (const float*)d_in[9];
    const float* bn2b = (const float*)d_in[10];
    const float* bn2m = (const float*)d_in[11];
    const float* bn2v = (const float*)d_in[12];
    float* out = (float*)d_out;

    nchw_to_nhwc<<<dim3(98, 8, BATCH), dim3(32, 8)>>>(x);
    transpose_w_big<<<2304, 256>>>(w1, 0);
    transpose_w_big<<<2304, 256>>>(w2, 1);
    transpose_w_off<<<288, 256>>>(woff);
    conv1_bnrelu<<<dim3(196, 2), 256>>>(bn1g, bn1b, bn1m, bn1v);
    conv_off<<<dim3(196, 1), 256>>>(offb);
    deform_bnrelu<<<dim3(196, 2), 256>>>(bn2g, bn2b, bn2m, bn2v, x, out);
}

// round 3
// speedup vs baseline: 1.0018x; 1.0018x over previous
#include <cuda_runtime.h>

#define BATCH 8
#define CH 256
#define HH 56
#define WW 56
#define HWSZ 3136     // 56*56
#define NPIX 25088    // BATCH*HWSZ, == 196*128 exactly
#define EPSBN 1e-5f

typedef unsigned long long ull;

__device__ __forceinline__ ull fma2(ull a, ull b, ull c) {
    ull d; asm("fma.rn.f32x2 %0, %1, %2, %3;" : "=l"(d) : "l"(a), "l"(b), "l"(c)); return d;
}
__device__ __forceinline__ ull mul2(ull a, ull b) {
    ull d; asm("mul.rn.f32x2 %0, %1, %2;" : "=l"(d) : "l"(a), "l"(b)); return d;
}
__device__ __forceinline__ ull dup2(float x) {
    ull d; asm("mov.b64 %0, {%1, %1};" : "=l"(d) : "f"(x)); return d;
}
__device__ __forceinline__ float2 unp2(ull v) {
    float2 r; asm("mov.b64 {%0, %1}, %2;" : "=f"(r.x), "=f"(r.y) : "l"(v)); return r;
}

// ---------------- scratch (device globals; no allocations allowed) -----------
static __device__ float g_xt[NPIX * CH];        // x in NHWC
static __device__ float g_out1[NPIX * CH];      // relu(bn1(conv1(x))) in NHWC
static __device__ float g_offs[NPIX * 18];      // offsets, [pix][18]
static __device__ float g_w1t[9 * CH * CH];     // conv1_w as [k][c][oc]
static __device__ float g_w2t[9 * CH * CH];     // conv2_w as [k][c][oc]
static __device__ float g_wofft[9 * CH * 32];   // off_w as [k][c][oc], oc padded 18->32

// ---------------- NCHW -> NHWC transpose of x --------------------------------
__global__ void nchw_to_nhwc(const float* __restrict__ x) {
    __shared__ float tile[32][33];
    const int b   = blockIdx.z;
    const int hw0 = blockIdx.x * 32;
    const int c0  = blockIdx.y * 32;
    const int tx = threadIdx.x, ty = threadIdx.y;
#pragma unroll
    for (int j = 0; j < 4; ++j)
        tile[ty + j * 8][tx] = x[(b * CH + c0 + ty + j * 8) * HWSZ + hw0 + tx];
    __syncthreads();
#pragma unroll
    for (int j = 0; j < 4; ++j)
        g_xt[(b * HWSZ + hw0 + ty + j * 8) * CH + c0 + tx] = tile[tx][ty + j * 8];
}

// ---------------- weight transposes OIHW -> [k][c][oc] -----------------------
__global__ void transpose_w_big(const float* __restrict__ w, int which) {
    const int idx = blockIdx.x * 256 + threadIdx.x;   // over [9][256][256]
    const int k  = idx / (CH * CH);
    const int r  = idx - k * CH * CH;
    const int c  = r >> 8;
    const int oc = r & 255;
    const float val = w[(oc * CH + c) * 9 + k];
    if (which) g_w2t[idx] = val; else g_w1t[idx] = val;
}

__global__ void transpose_w_off(const float* __restrict__ w) {
    const int idx = blockIdx.x * 256 + threadIdx.x;   // over [9][256][32]
    const int k  = idx / (CH * 32);
    const int r  = idx - k * CH * 32;
    const int c  = r >> 5;
    const int oc = r & 31;
    g_wofft[idx] = (oc < 18) ? w[(oc * CH + c) * 9 + k] : 0.f;
}

// ---------------- conv1 (3x3, 256->256) + BN1 + ReLU, NHWC -> NHWC -----------
// BM=128 pixels, BN=128 out-channels, BK=16, 256 threads, 8x8 tile via f32x2.
__global__ __launch_bounds__(256, 2)
void conv1_bnrelu(const float* __restrict__ bg, const float* __restrict__ bbeta,
                  const float* __restrict__ bm, const float* __restrict__ bv) {
    __shared__ __align__(16) float As[16][132];
    __shared__ __align__(16) float Bs[16][132];
    const int tid     = threadIdx.x;
    const int pixbase = blockIdx.x * 128;
    const int octile  = blockIdx.y * 128;

    const int pA0 = tid >> 2;              // pixel 0..63 (and +64)
    const int cA  = (tid & 3) << 2;        // channel-within-slice 0,4,8,12
    const int gp0 = pixbase + pA0;
    const int gp1 = gp0 + 64;
    const int b0 = gp0 / HWSZ; const int r0 = gp0 - b0 * HWSZ;
    const int b1 = gp1 / HWSZ; const int r1 = gp1 - b1 * HWSZ;
    const int py0 = r0 / WW, px0 = r0 - (r0 / WW) * WW;
    const int py1 = r1 / WW, px1 = r1 - (r1 / WW) * WW;

    const int ccB = tid >> 5;              // 0..7 (and +8)
    const int ocB = (tid & 31) << 2;       // 0..124

    const int txc = tid & 15, tyc = tid >> 4;
    const int o0 = txc << 3, p0 = tyc << 3;

    ull accP[4][8];
#pragma unroll
    for (int i = 0; i < 4; ++i)
#pragma unroll
        for (int j = 0; j < 8; ++j) accP[i][j] = 0ull;

    for (int k = 0; k < 9; ++k) {
        const int ky = k / 3, kx = k - (k / 3) * 3;
        const int sy0 = py0 + ky - 1, sx0 = px0 + kx - 1;
        const int sy1 = py1 + ky - 1, sx1 = px1 + kx - 1;
        const bool v0 = ((unsigned)sy0 < HH) & ((unsigned)sx0 < WW);
        const bool v1 = ((unsigned)sy1 < HH) & ((unsigned)sx1 < WW);
        const float* pa0 = g_xt + ((b0 * HWSZ + sy0 * WW + sx0) << 8) + cA;
        const float* pa1 = g_xt + ((b1 * HWSZ + sy1 * WW + sx1) << 8) + cA;
        const float* pw  = g_w1t + ((k * CH + ccB) << 8) + octile + ocB;

        for (int c0 = 0; c0 < CH; c0 += 16) {
            float4 a0 = make_float4(0.f, 0.f, 0.f, 0.f);
            float4 a1 = make_float4(0.f, 0.f, 0.f, 0.f);
            if (v0) a0 = *(const float4*)(pa0 + c0);
            if (v1) a1 = *(const float4*)(pa1 + c0);
            const float4 w0 = *(const float4*)(pw + (c0 << 8));
            const float4 w1 = *(const float4*)(pw + ((c0 + 8) << 8));
            __syncthreads();
            As[cA + 0][pA0] = a0.x; As[cA + 1][pA0] = a0.y;
            As[cA + 2][pA0] = a0.z; As[cA + 3][pA0] = a0.w;
            As[cA + 0][pA0 + 64] = a1.x; As[cA + 1][pA0 + 64] = a1.y;
            As[cA + 2][pA0 + 64] = a1.z; As[cA + 3][pA0 + 64] = a1.w;
            *(float4*)&Bs[ccB][ocB]     = w0;
            *(float4*)&Bs[ccB + 8][ocB] = w1;
            __syncthreads();
#pragma unroll
            for (int cc = 0; cc < 16; ++cc) {
                const ulonglong2 aA = *(const ulonglong2*)&As[cc][p0];
                const ulonglong2 aB = *(const ulonglong2*)&As[cc][p0 + 4];
                const float4 blo = *(const float4*)&Bs[cc][o0];
                const float4 bhi = *(const float4*)&Bs[cc][o0 + 4];
                const ull ap[4] = {aA.x, aA.y, aB.x, aB.y};
                const ull bd[8] = {dup2(blo.x), dup2(blo.y), dup2(blo.z), dup2(blo.w),
                                   dup2(bhi.x), dup2(bhi.y), dup2(bhi.z), dup2(bhi.w)};
#pragma unroll
                for (int i = 0; i < 4; ++i)
#pragma unroll
                    for (int j = 0; j < 8; ++j)
                        accP[i][j] = fma2(ap[i], bd[j], accP[i][j]);
            }
        }
    }

    float inv[8], bet[8];
#pragma unroll
    for (int j = 0; j < 8; ++j) {
        const int oc = octile + o0 + j;
        const float iv = bg[oc] * rsqrtf(bv[oc] + EPSBN);
        inv[j] = iv;
        bet[j] = bbeta[oc] - bm[oc] * iv;
    }
#pragma unroll
    for (int i2 = 0; i2 < 4; ++i2) {
        float r0v[8], r1v[8];
#pragma unroll
        for (int j = 0; j < 8; ++j) {
            const float2 v = unp2(accP[i2][j]);
            r0v[j] = fmaxf(fmaf(v.x, inv[j], bet[j]), 0.f);
            r1v[j] = fmaxf(fmaf(v.y, inv[j], bet[j]), 0.f);
        }
        const int gpa = pixbase + p0 + 2 * i2;
        *(float4*)&g_out1[gpa * CH + octile + o0]           = *(float4*)&r0v[0];
        *(float4*)&g_out1[gpa * CH + octile + o0 + 4]       = *(float4*)&r0v[4];
        *(float4*)&g_out1[(gpa + 1) * CH + octile + o0]     = *(float4*)&r1v[0];
        *(float4*)&g_out1[(gpa + 1) * CH + octile + o0 + 4] = *(float4*)&r1v[4];
    }
}

// ---------------- offset conv (3x3, 256->18 padded to 32) --------------------
__global__ __launch_bounds__(256, 2)
void conv_off(const float* __restrict__ offb) {
    __shared__ __align__(16) float As[16][132];
    __shared__ __align__(16) float Bs[16][36];
    const int tid     = threadIdx.x;
    const int pixbase = blockIdx.x * 128;

    const int pA0 = tid >> 2;
    const int cA  = (tid & 3) << 2;
    const int gp0 = pixbase + pA0;
    const int gp1 = gp0 + 64;
    const int b0 = gp0 / HWSZ; const int r0 = gp0 - b0 * HWSZ;
    const int b1 = gp1 / HWSZ; const int r1 = gp1 - b1 * HWSZ;
    const int py0 = r0 / WW, px0 = r0 - (r0 / WW) * WW;
    const int py1 = r1 / WW, px1 = r1 - (r1 / WW) * WW;

    const int ccB = tid >> 3;          // valid when tid<128: 0..15
    const int ocB = (tid & 7) << 2;    // 0..28

    const int txc = tid & 15, tyc = tid >> 4;
    const int o0 = txc << 1, p0 = tyc << 3;

    ull accP[4][2];
#pragma unroll
    for (int i = 0; i < 4; ++i) { accP[i][0] = 0ull; accP[i][1] = 0ull; }

    for (int k = 0; k < 9; ++k) {
        const int ky = k / 3, kx = k - (k / 3) * 3;
        const int sy0 = py0 + ky - 1, sx0 = px0 + kx - 1;
        const int sy1 = py1 + ky - 1, sx1 = px1 + kx - 1;
        const bool v0 = ((unsigned)sy0 < HH) & ((unsigned)sx0 < WW);
        const bool v1 = ((unsigned)sy1 < HH) & ((unsigned)sx1 < WW);
        const float* pa0 = g_out1 + ((b0 * HWSZ + sy0 * WW + sx0) << 8) + cA;
        const float* pa1 = g_out1 + ((b1 * HWSZ + sy1 * WW + sx1) << 8) + cA;

        for (int c0 = 0; c0 < CH; c0 += 16) {
            float4 a0 = make_float4(0.f, 0.f, 0.f, 0.f);
            float4 a1 = make_float4(0.f, 0.f, 0.f, 0.f);
            if (v0) a0 = *(const float4*)(pa0 + c0);
            if (v1) a1 = *(const float4*)(pa1 + c0);
            float4 wv = make_float4(0.f, 0.f, 0.f, 0.f);
            if (tid < 128) wv = *(const float4*)(g_wofft + (k * CH + c0 + ccB) * 32 + ocB);
            __syncthreads();
            As[cA + 0][pA0] = a0.x; As[cA + 1][pA0] = a0.y;
            As[cA + 2][pA0] = a0.z; As[cA + 3][pA0] = a0.w;
            As[cA + 0][pA0 + 64] = a1.x; As[cA + 1][pA0 + 64] = a1.y;
            As[cA + 2][pA0 + 64] = a1.z; As[cA + 3][pA0 + 64] = a1.w;
            if (tid < 128) *(float4*)&Bs[ccB][ocB] = wv;
            __syncthreads();
#pragma unroll
            for (int cc = 0; cc < 16; ++cc) {
                const ulonglong2 aA = *(const ulonglong2*)&As[cc][p0];
                const ulonglong2 aB = *(const ulonglong2*)&As[cc][p0 + 4];
                const float2 bv2 = *(const float2*)&Bs[cc][o0];
                const ull ap[4] = {aA.x, aA.y, aB.x, aB.y};
                const ull bd0 = dup2(bv2.x), bd1 = dup2(bv2.y);
#pragma unroll
                for (int i = 0; i < 4; ++i) {
                    accP[i][0] = fma2(ap[i], bd0, accP[i][0]);
                    accP[i][1] = fma2(ap[i], bd1, accP[i][1]);
                }
            }
        }
    }

    if (o0 < 18) {
        const float bo0 = offb[o0], bo1 = offb[o0 + 1];
#pragma unroll
        for (int i2 = 0; i2 < 4; ++i2) {
            const float2 v0 = unp2(accP[i2][0]);
            const float2 v1 = unp2(accP[i2][1]);
            const int gpa = pixbase + p0 + 2 * i2;
            g_offs[gpa * 18 + o0]           = v0.x + bo0;
            g_offs[gpa * 18 + o0 + 1]       = v1.x + bo1;
            g_offs[(gpa + 1) * 18 + o0]     = v0.y + bo0;
            g_offs[(gpa + 1) * 18 + o0 + 1] = v1.y + bo1;
        }
    }
}

// ---------------- deformable conv + BN2 + residual + ReLU --------------------
__global__ __launch_bounds__(256, 2)
void deform_bnrelu(const float* __restrict__ bg, const float* __restrict__ bbeta,
                   const float* __restrict__ bm, const float* __restrict__ bv,
                   const float* __restrict__ resid, float* __restrict__ out) {
    __shared__ __align__(16) float As[16][132];
    __shared__ __align__(16) float Bs[16][132];
    __shared__ float4 cw[128 * 9];   // bilinear corner weights (validity-masked)
    __shared__ int   cpk[128 * 9];   // packed clamped corner coords

    const int tid     = threadIdx.x;
    const int pixbase = blockIdx.x * 128;
    const int octile  = blockIdx.y * 128;

    for (int idx = tid; idx < 128 * 9; idx += 256) {
        const int p = idx / 9, k = idx - (idx / 9) * 9;
        const int gp = pixbase + p;
        const int b = gp / HWSZ; const int rem = gp - b * HWSZ;
        const int yy = rem / WW; const int xx = rem - yy * WW;
        const float oy = g_offs[gp * 18 + k];
        const float ox = g_offs[gp * 18 + 9 + k];
        const float ys = (float)(yy + k / 3 - 1) + oy;
        const float xs = (float)(xx + (k - (k / 3) * 3) - 1) + ox;
        const float yf = floorf(ys), xf = floorf(xs);
        const float ty = ys - yf, tx = xs - xf;
        const int iy0 = (int)yf, ix0 = (int)xf;
        const int iy1 = iy0 + 1, ix1 = ix0 + 1;
        const float vy0 = ((unsigned)iy0 < HH) ? 1.f : 0.f;
        const float vy1 = ((unsigned)iy1 < HH) ? 1.f : 0.f;
        const float vx0 = ((unsigned)ix0 < WW) ? 1.f : 0.f;
        const float vx1 = ((unsigned)ix1 < WW) ? 1.f : 0.f;
        cw[idx] = make_float4((1.f - ty) * (1.f - tx) * vy0 * vx0,
                              (1.f - ty) * tx         * vy0 * vx1,
                              ty         * (1.f - tx) * vy1 * vx0,
                              ty         * tx         * vy1 * vx1);
        const int cy0 = min(max(iy0, 0), HH - 1), cy1 = min(max(iy1, 0), HH - 1);
        const int cx0 = min(max(ix0, 0), WW - 1), cx1 = min(max(ix1, 0), WW - 1);
        cpk[idx] = cy0 | (cx0 << 8) | (cy1 << 16) | (cx1 << 24);
    }
    __syncthreads();

    const int pA0 = tid >> 2;
    const int cA  = (tid & 3) << 2;
    const int gp0 = pixbase + pA0, gp1 = gp0 + 64;
    const int bb0 = (gp0 / HWSZ) * HWSZ;
    const int bb1 = (gp1 / HWSZ) * HWSZ;
    const int ccB = tid >> 5;
    const int ocB = (tid & 31) << 2;
    const int txc = tid & 15, tyc = tid >> 4;
    const int o0 = txc << 3, p0 = tyc << 3;
    const float* gin = g_out1 + cA;

    ull accP[4][8];
#pragma unroll
    for (int i = 0; i < 4; ++i)
#pragma unroll
        for (int j = 0; j < 8; ++j) accP[i][j] = 0ull;

    for (int k = 0; k < 9; ++k) {
        const float4 wA0 = cw[pA0 * 9 + k];
        const int    pk0 = cpk[pA0 * 9 + k];
        const float4 wA1 = cw[(pA0 + 64) * 9 + k];
        const int    pk1 = cpk[(pA0 + 64) * 9 + k];
        const int b00_0 = (bb0 + (pk0 & 255) * WW + ((pk0 >> 8) & 255)) << 8;
        const int b01_0 = (bb0 + (pk0 & 255) * WW + ((pk0 >> 24) & 255)) << 8;
        const int b10_0 = (bb0 + ((pk0 >> 16) & 255) * WW + ((pk0 >> 8) & 255)) << 8;
        const int b11_0 = (bb0 + ((pk0 >> 16) & 255) * WW + ((pk0 >> 24) & 255)) << 8;
        const int b00_1 = (bb1 + (pk1 & 255) * WW + ((pk1 >> 8) & 255)) << 8;
        const int b01_1 = (bb1 + (pk1 & 255) * WW + ((pk1 >> 24) & 255)) << 8;
        const int b10_1 = (bb1 + ((pk1 >> 16) & 255) * WW + ((pk1 >> 8) & 255)) << 8;
        const int b11_1 = (bb1 + ((pk1 >> 16) & 255) * WW + ((pk1 >> 24) & 255)) << 8;
        const float* pw = g_w2t + ((k * CH + ccB) << 8) + octile + ocB;

        // hoisted duplicated bilinear weights for packed math
        const ull w0x = dup2(wA0.x), w0y = dup2(wA0.y), w0z = dup2(wA0.z), w0w = dup2(wA0.w);
        const ull w1x = dup2(wA1.x), w1y = dup2(wA1.y), w1z = dup2(wA1.z), w1w = dup2(wA1.w);

        for (int c0 = 0; c0 < CH; c0 += 16) {
            const ulonglong2 s00 = *(const ulonglong2*)(gin + b00_0 + c0);
            const ulonglong2 s01 = *(const ulonglong2*)(gin + b01_0 + c0);
            const ulonglong2 s10 = *(const ulonglong2*)(gin + b10_0 + c0);
            const ulonglong2 s11 = *(const ulonglong2*)(gin + b11_0 + c0);
            const ull a0lo = fma2(w0x, s00.x, fma2(w0y, s01.x, fma2(w0z, s10.x, mul2(w0w, s11.x))));
            const ull a0hi = fma2(w0x, s00.y, fma2(w0y, s01.y, fma2(w0z, s10.y, mul2(w0w, s11.y))));
            const ulonglong2 t00 = *(const ulonglong2*)(gin + b00_1 + c0);
            const ulonglong2 t01 = *(const ulonglong2*)(gin + b01_1 + c0);
            const ulonglong2 t10 = *(const ulonglong2*)(gin + b10_1 + c0);
            const ulonglong2 t11 = *(const ulonglong2*)(gin + b11_1 + c0);
            const ull a1lo = fma2(w1x, t00.x, fma2(w1y, t01.x, fma2(w1z, t10.x, mul2(w1w, t11.x))));
            const ull a1hi = fma2(w1x, t00.y, fma2(w1y, t01.y, fma2(w1z, t10.y, mul2(w1w, t11.y))));
            const float4 w0 = *(const float4*)(pw + (c0 << 8));
            const float4 w1 = *(const float4*)(pw + ((c0 + 8) << 8));
            __syncthreads();
            {
                const float2 u0 = unp2(a0lo), u1 = unp2(a0hi);
                As[cA + 0][pA0] = u0.x; As[cA + 1][pA0] = u0.y;
                As[cA + 2][pA0] = u1.x; As[cA + 3][pA0] = u1.y;
                const float2 u2 = unp2(a1lo), u3 = unp2(a1hi);
                As[cA + 0][pA0 + 64] = u2.x; As[cA + 1][pA0 + 64] = u2.y;
                As[cA + 2][pA0 + 64] = u3.x; As[cA + 3][pA0 + 64] = u3.y;
            }
            *(float4*)&Bs[ccB][ocB]     = w0;
            *(float4*)&Bs[ccB + 8][ocB] = w1;
            __syncthreads();
#pragma unroll
            for (int cc = 0; cc < 16; ++cc) {
                const ulonglong2 aA = *(const ulonglong2*)&As[cc][p0];
                const ulonglong2 aB = *(const ulonglong2*)&As[cc][p0 + 4];
                const float4 blo = *(const float4*)&Bs[cc][o0];
                const float4 bhi = *(const float4*)&Bs[cc][o0 + 4];
                const ull ap[4] = {aA.x, aA.y, aB.x, aB.y};
                const ull bd[8] = {dup2(blo.x), dup2(blo.y), dup2(blo.z), dup2(blo.w),
                                   dup2(bhi.x), dup2(bhi.y), dup2(bhi.z), dup2(bhi.w)};
#pragma unroll
                for (int i = 0; i < 4; ++i)
#pragma unroll
                    for (int j = 0; j < 8; ++j)
                        accP[i][j] = fma2(ap[i], bd[j], accP[i][j]);
            }
        }
    }

    float inv[8], bet[8];
#pragma unroll
    for (int j = 0; j < 8; ++j) {
        const int oc = octile + o0 + j;
        const float iv = bg[oc] * rsqrtf(bv[oc] + EPSBN);
        inv[j] = iv;
        bet[j] = bbeta[oc] - bm[oc] * iv;
    }
#pragma unroll
    for (int i2 = 0; i2 < 4; ++i2) {
        const int gpa = pixbase + p0 + 2 * i2;
        const int ba = gpa / HWSZ; const int rema = gpa - ba * HWSZ;
        const int base0 = ba * (CH * HWSZ) + rema;
        const int gpb = gpa + 1;
        const int bb = gpb / HWSZ; const int remb = gpb - bb * HWSZ;
        const int base1 = bb * (CH * HWSZ) + remb;
#pragma unroll
        for (int j = 0; j < 8; ++j) {
            const float2 v = unp2(accP[i2][j]);
            const int a0 = base0 + (octile + o0 + j) * HWSZ;
            const int a1 = base1 + (octile + o0 + j) * HWSZ;
            out[a0] = fmaxf(fmaf(v.x, inv[j], bet[j]) + resid[a0], 0.f);
            out[a1] = fmaxf(fmaf(v.y, inv[j], bet[j]) + resid[a1], 0.f);
        }
    }
}

// ---------------- launch ------------------------------------------------------
extern "C" void kernel_launch(void* const* d_in, const int* in_sizes, int n_in,
                              void* d_out, int out_size) {
    const float* x    = (const float*)d_in[0];
    const float* w1   = (const float*)d_in[1];
    const float* bn1g = (const float*)d_in[2];
    const float* bn1b = (const float*)d_in[3];
    const float* bn1m = (const float*)d_in[4];
    const float* bn1v = (const float*)d_in[5];
    const float* woff = (const float*)d_in[6];
    const float* offb = (const float*)d_in[7];
    const float* w2   = (const float*)d_in[8];
    const float* bn2g = (const float*)d_in[9];
    const float* bn2b = (const float*)d_in[10];
    const float* bn2m = (const float*)d_in[11];
    const float* bn2v = (const float*)d_in[12];
    float* out = (float*)d_out;

    nchw_to_nhwc<<<dim3(98, 8, BATCH), dim3(32, 8)>>>(x);
    transpose_w_big<<<2304, 256>>>(w1, 0);
    transpose_w_big<<<2304, 256>>>(w2, 1);
    transpose_w_off<<<288, 256>>>(woff);
    conv1_bnrelu<<<dim3(196, 2), 256>>>(bn1g, bn1b, bn1m, bn1v);
    conv_off<<<dim3(196, 1), 256>>>(offb);
    deform_bnrelu<<<dim3(196, 2), 256>>>(bn2g, bn2b, bn2m, bn2v, x, out);
}

// round 5
// speedup vs baseline: 1.6537x; 1.6508x over previous
#include <cuda_runtime.h>
#include <cuda_bf16.h>
#include <cstdint>

#define BATCH 8
#define CH 256
#define HH 56
#define WW 56
#define HWSZ 3136
#define NPIX 25088     // 196 * 128
#define EPSBN 1e-5f
#define PADB 80        // smem row pitch (bytes) for 32-ch bf16 rows: conflict-free ldmatrix

typedef unsigned int u32;

// ---------------- device scratch ----------------
static __device__ __nv_bfloat16 g_xh[NPIX * CH], g_xl[NPIX * CH];   // x NHWC hi/lo
static __device__ float         g_out1f[NPIX * CH];                 // out1 NHWC fp32
static __device__ __nv_bfloat16 g_o1h[NPIX * CH], g_o1l[NPIX * CH]; // out1 hi/lo
static __device__ float         g_offs[NPIX * 18];
static __device__ __nv_bfloat16 g_w1h[9 * CH * CH], g_w1l[9 * CH * CH]; // [k][oc][c]
static __device__ __nv_bfloat16 g_w2h[9 * CH * CH], g_w2l[9 * CH * CH];
static __device__ __nv_bfloat16 g_woh[9 * 32 * CH], g_wol[9 * 32 * CH]; // [k][oc32][c]

// ---------------- helpers ----------------
__device__ __forceinline__ u32 smem_u32(const void* p) {
    u32 a;
    asm("{ .reg .u64 t; cvta.to.shared.u64 t, %1; cvt.u32.u64 %0, t; }" : "=r"(a) : "l"(p));
    return a;
}
__device__ __forceinline__ void ldm4(u32 addr, u32* r) {
    asm volatile("ldmatrix.sync.aligned.m8n8.x4.shared.b16 {%0,%1,%2,%3}, [%4];"
                 : "=r"(r[0]), "=r"(r[1]), "=r"(r[2]), "=r"(r[3]) : "r"(addr));
}
__device__ __forceinline__ void mma_bf16(float* c, const u32* a, u32 b0, u32 b1) {
    asm volatile(
        "mma.sync.aligned.m16n8k16.row.col.f32.bf16.bf16.f32 "
        "{%0,%1,%2,%3}, {%4,%5,%6,%7}, {%8,%9}, {%0,%1,%2,%3};"
        : "+f"(c[0]), "+f"(c[1]), "+f"(c[2]), "+f"(c[3])
        : "r"(a[0]), "r"(a[1]), "r"(a[2]), "r"(a[3]), "r"(b0), "r"(b1));
}
__device__ __forceinline__ void split_bf16(float v, __nv_bfloat16& h, __nv_bfloat16& l) {
    h = __float2bfloat16(v);
    l = __float2bfloat16(v - __bfloat162float(h));
}

// ---------------- prep kernels ----------------
__global__ void prep_x(const float* __restrict__ x) {
    __shared__ float tile[32][33];
    const int b = blockIdx.z, hw0 = blockIdx.x * 32, c0 = blockIdx.y * 32;
    const int tx = threadIdx.x, ty = threadIdx.y;
#pragma unroll
    for (int j = 0; j < 4; ++j)
        tile[ty + j * 8][tx] = x[(b * CH + c0 + ty + j * 8) * HWSZ + hw0 + tx];
    __syncthreads();
#pragma unroll
    for (int j = 0; j < 4; ++j) {
        const float v = tile[tx][ty + j * 8];
        const int pix = b * HWSZ + hw0 + ty + j * 8;
        __nv_bfloat16 h, l; split_bf16(v, h, l);
        g_xh[pix * CH + c0 + tx] = h;
        g_xl[pix * CH + c0 + tx] = l;
    }
}

__global__ void prep_w(const float* __restrict__ w, int which) {
    const int idx = blockIdx.x * 256 + threadIdx.x;   // 9*256*256
    const int k = idx >> 16, r = idx & 65535, oc = r >> 8, c = r & 255;
    const float v = w[(oc * CH + c) * 9 + k];
    __nv_bfloat16 h, l; split_bf16(v, h, l);
    const int o = (k * CH + oc) * CH + c;
    if (which) { g_w2h[o] = h; g_w2l[o] = l; } else { g_w1h[o] = h; g_w1l[o] = l; }
}

__global__ void prep_woff(const float* __restrict__ w) {
    const int idx = blockIdx.x * 256 + threadIdx.x;   // 9*32*256
    const int k = idx >> 13, r = idx & 8191, oc = r >> 8, c = r & 255;
    const float v = (oc < 18) ? w[(oc * CH + c) * 9 + k] : 0.f;
    __nv_bfloat16 h, l; split_bf16(v, h, l);
    const int o = (k * 32 + oc) * CH + c;
    g_woh[o] = h; g_wol[o] = l;
}

// ================= conv1: mma.sync, 128px x 128oc per CTA =================
#define C1_BUF 40960
#define C1_AH 0
#define C1_AL 10240
#define C1_BH 20480
#define C1_BL 30720
#define C1_IB 81920
#define C1_SZ 83968

__global__ __launch_bounds__(256)
void conv1_mma(const float* __restrict__ bg, const float* __restrict__ bb_,
               const float* __restrict__ bm, const float* __restrict__ bv) {
    extern __shared__ __align__(16) char S[];
    const int tid = threadIdx.x, lane = tid & 31, wid = tid >> 5;
    const int pixbase = blockIdx.x * 128, octile = blockIdx.y * 128;
    const u32 sb = smem_u32(S);
    float* invbet = (float*)(S + C1_IB);
    {
        const float iv = bg[tid] * rsqrtf(bv[tid] + EPSBN);
        invbet[tid] = iv;
        invbet[256 + tid] = bb_[tid] - bm[tid] * iv;
    }

    const int arow = tid >> 1, ah = tid & 1;
    const int gp = pixbase + arow;
    const int bIdx = gp / HWSZ, rem = gp - bIdx * HWSZ;
    const int py = rem / WW, px = rem - (rem / WW) * WW;
    const int pixrowbase = bIdx * HWSZ;
    const u32 so = (u32)(arow * PADB + ah * 32);

    const int wm = wid >> 2, wn = wid & 3;
    float acc[4][4][4];
#pragma unroll
    for (int a = 0; a < 4; ++a)
#pragma unroll
        for (int b = 0; b < 4; ++b)
#pragma unroll
            for (int c = 0; c < 4; ++c) acc[a][b][c] = 0.f;

    uint4 pAh[2], pAl[2], pBh[2], pBl[2];

    auto LOAD = [&](int i) {
        const int k = i >> 3, c0 = (i & 7) << 5, cc = c0 + ah * 16;
        const int ky = k / 3, kx = k - (k / 3) * 3;
        const int sy = py + ky - 1, sx = px + kx - 1;
        if (((unsigned)sy < HH) & ((unsigned)sx < WW)) {
            const int gb = ((pixrowbase + sy * WW + sx) << 8) + cc;
            pAh[0] = *(const uint4*)(g_xh + gb); pAh[1] = *(const uint4*)(g_xh + gb + 8);
            pAl[0] = *(const uint4*)(g_xl + gb); pAl[1] = *(const uint4*)(g_xl + gb + 8);
        } else {
            pAh[0] = pAh[1] = pAl[0] = pAl[1] = make_uint4(0, 0, 0, 0);
        }
        const int wb = ((k * CH + octile + arow) << 8) + cc;
        pBh[0] = *(const uint4*)(g_w1h + wb); pBh[1] = *(const uint4*)(g_w1h + wb + 8);
        pBl[0] = *(const uint4*)(g_w1l + wb); pBl[1] = *(const uint4*)(g_w1l + wb + 8);
    };
    auto STORE = [&](int buf) {
        char* B0 = S + buf * C1_BUF;
        *(uint4*)(B0 + C1_AH + so) = pAh[0]; *(uint4*)(B0 + C1_AH + so + 16) = pAh[1];
        *(uint4*)(B0 + C1_AL + so) = pAl[0]; *(uint4*)(B0 + C1_AL + so + 16) = pAl[1];
        *(uint4*)(B0 + C1_BH + so) = pBh[0]; *(uint4*)(B0 + C1_BH + so + 16) = pBh[1];
        *(uint4*)(B0 + C1_BL + so) = pBl[0]; *(uint4*)(B0 + C1_BL + so + 16) = pBl[1];
    };

    const u32 aab = sb + (u32)((wm * 64 + (lane & 15)) * PADB + (lane >> 4) * 16);
    const u32 bab = sb + C1_BH +
        (u32)((wn * 32 + ((lane >> 4) << 3) + (lane & 7)) * PADB + ((lane >> 3) & 1) * 16);

    auto COMP = [&](int buf) {
        const u32 ab = aab + buf * C1_BUF, bbx = bab + buf * C1_BUF;
#pragma unroll
        for (int s = 0; s < 2; ++s) {
            const u32 ko = s * 32;
            u32 bh0[4], bh1[4], bl0[4], bl1[4];
            ldm4(bbx + ko, bh0);
            ldm4(bbx + 16 * PADB + ko, bh1);
            ldm4(bbx + (C1_BL - C1_BH) + ko, bl0);
            ldm4(bbx + (C1_BL - C1_BH) + 16 * PADB + ko, bl1);
            u32 ahf[4][4], alf[4][4];
#pragma unroll
            for (int mt = 0; mt < 4; ++mt) {
                ldm4(ab + mt * 16 * PADB + ko, ahf[mt]);
                ldm4(ab + (C1_AL - C1_AH) + mt * 16 * PADB + ko, alf[mt]);
            }
#pragma unroll
            for (int mt = 0; mt < 4; ++mt)
#pragma unroll
                for (int nt = 0; nt < 4; ++nt) {
                    u32* bhq = (nt < 2) ? bh0 : bh1;
                    u32* blq = (nt < 2) ? bl0 : bl1;
                    const int h = (nt & 1) * 2;
                    mma_bf16(acc[mt][nt], ahf[mt], bhq[h], bhq[h + 1]);
                    mma_bf16(acc[mt][nt], ahf[mt], blq[h], blq[h + 1]);
                    mma_bf16(acc[mt][nt], alf[mt], bhq[h], bhq[h + 1]);
                }
        }
    };

    LOAD(0); STORE(0); __syncthreads();
    for (int i = 0; i < 72; ++i) {
        if (i < 71) LOAD(i + 1);
        COMP(i & 1);
        if (i < 71) STORE((i + 1) & 1);
        __syncthreads();
    }

    const int g = lane >> 2, t2 = (lane & 3) * 2;
#pragma unroll
    for (int mt = 0; mt < 4; ++mt) {
        const int pr = pixbase + wm * 64 + mt * 16 + g;
#pragma unroll
        for (int nt = 0; nt < 4; ++nt) {
            const int oc = octile + wn * 32 + nt * 8 + t2;
            const float i0 = invbet[oc], i1 = invbet[oc + 1];
            const float e0 = invbet[256 + oc], e1 = invbet[256 + oc + 1];
            const float v00 = fmaxf(fmaf(acc[mt][nt][0], i0, e0), 0.f);
            const float v01 = fmaxf(fmaf(acc[mt][nt][1], i1, e1), 0.f);
            const float v10 = fmaxf(fmaf(acc[mt][nt][2], i0, e0), 0.f);
            const float v11 = fmaxf(fmaf(acc[mt][nt][3], i1, e1), 0.f);
            *(float2*)(g_out1f + pr * CH + oc) = make_float2(v00, v01);
            *(float2*)(g_out1f + (pr + 8) * CH + oc) = make_float2(v10, v11);
            __nv_bfloat16 h0, l0, h1, l1;
            __nv_bfloat162 th, tl;
            split_bf16(v00, h0, l0); split_bf16(v01, h1, l1);
            th.x = h0; th.y = h1; tl.x = l0; tl.y = l1;
            *(__nv_bfloat162*)(g_o1h + pr * CH + oc) = th;
            *(__nv_bfloat162*)(g_o1l + pr * CH + oc) = tl;
            split_bf16(v10, h0, l0); split_bf16(v11, h1, l1);
            th.x = h0; th.y = h1; tl.x = l0; tl.y = l1;
            *(__nv_bfloat162*)(g_o1h + (pr + 8) * CH + oc) = th;
            *(__nv_bfloat162*)(g_o1l + (pr + 8) * CH + oc) = tl;
        }
    }
}

// ================= offset conv: 128px x 32oc =================
#define OF_BUF 25600
#define OF_AH 0
#define OF_AL 10240
#define OF_BH 20480
#define OF_BL 23040
#define OF_OB 51200
#define OF_SZ 51328

__global__ __launch_bounds__(256)
void convoff_mma(const float* __restrict__ offb) {
    extern __shared__ __align__(16) char S[];
    const int tid = threadIdx.x, lane = tid & 31, wid = tid >> 5;
    const int pixbase = blockIdx.x * 128;
    const u32 sb = smem_u32(S);
    float* obs = (float*)(S + OF_OB);
    if (tid < 32) obs[tid] = (tid < 18) ? offb[tid] : 0.f;

    const int arow = tid >> 1, ah = tid & 1;
    const int gp = pixbase + arow;
    const int bIdx = gp / HWSZ, rem = gp - bIdx * HWSZ;
    const int py = rem / WW, px = rem - (rem / WW) * WW;
    const int pixrowbase = bIdx * HWSZ;
    const u32 so = (u32)(arow * PADB + ah * 32);

    const int wm = wid >> 1, wn = wid & 1;
    float acc[2][2][4];
#pragma unroll
    for (int a = 0; a < 2; ++a)
#pragma unroll
        for (int b = 0; b < 2; ++b)
#pragma unroll
            for (int c = 0; c < 4; ++c) acc[a][b][c] = 0.f;

    uint4 pAh[2], pAl[2], pBh[2], pBl[2];

    auto LOAD = [&](int i) {
        const int k = i >> 3, c0 = (i & 7) << 5, cc = c0 + ah * 16;
        const int ky = k / 3, kx = k - (k / 3) * 3;
        const int sy = py + ky - 1, sx = px + kx - 1;
        if (((unsigned)sy < HH) & ((unsigned)sx < WW)) {
            const int gb = ((pixrowbase + sy * WW + sx) << 8) + cc;
            pAh[0] = *(const uint4*)(g_o1h + gb); pAh[1] = *(const uint4*)(g_o1h + gb + 8);
            pAl[0] = *(const uint4*)(g_o1l + gb); pAl[1] = *(const uint4*)(g_o1l + gb + 8);
        } else {
            pAh[0] = pAh[1] = pAl[0] = pAl[1] = make_uint4(0, 0, 0, 0);
        }
        if (tid < 64) {
            const int wb = ((k * 32 + arow) << 8) + cc;
            pBh[0] = *(const uint4*)(g_woh + wb); pBh[1] = *(const uint4*)(g_woh + wb + 8);
            pBl[0] = *(const uint4*)(g_wol + wb); pBl[1] = *(const uint4*)(g_wol + wb + 8);
        }
    };
    auto STORE = [&](int buf) {
        char* B0 = S + buf * OF_BUF;
        *(uint4*)(B0 + OF_AH + so) = pAh[0]; *(uint4*)(B0 + OF_AH + so + 16) = pAh[1];
        *(uint4*)(B0 + OF_AL + so) = pAl[0]; *(uint4*)(B0 + OF_AL + so + 16) = pAl[1];
        if (tid < 64) {
            *(uint4*)(B0 + OF_BH + so) = pBh[0]; *(uint4*)(B0 + OF_BH + so + 16) = pBh[1];
            *(uint4*)(B0 + OF_BL + so) = pBl[0]; *(uint4*)(B0 + OF_BL + so + 16) = pBl[1];
        }
    };

    const u32 aab = sb + (u32)((wm * 32 + (lane & 15)) * PADB + (lane >> 4) * 16);
    const u32 bab = sb + OF_BH +
        (u32)((wn * 16 + ((lane >> 4) << 3) + (lane & 7)) * PADB + ((lane >> 3) & 1) * 16);

    auto COMP = [&](int buf) {
        const u32 ab = aab + buf * OF_BUF, bbx = bab + buf * OF_BUF;
#pragma unroll
        for (int s = 0; s < 2; ++s) {
            const u32 ko = s * 32;
            u32 bh[4], bl[4];
            ldm4(bbx + ko, bh);
            ldm4(bbx + (OF_BL - OF_BH) + ko, bl);
            u32 ahf[2][4], alf[2][4];
#pragma unroll
            for (int mt = 0; mt < 2; ++mt) {
                ldm4(ab + mt * 16 * PADB + ko, ahf[mt]);
                ldm4(ab + (OF_AL - OF_AH) + mt * 16 * PADB + ko, alf[mt]);
            }
#pragma unroll
            for (int mt = 0; mt < 2; ++mt)
#pragma unroll
                for (int nt = 0; nt < 2; ++nt) {
                    const int h = nt * 2;
                    mma_bf16(acc[mt][nt], ahf[mt], bh[h], bh[h + 1]);
                    mma_bf16(acc[mt][nt], ahf[mt], bl[h], bl[h + 1]);
                    mma_bf16(acc[mt][nt], alf[mt], bh[h], bh[h + 1]);
                }
        }
    };

    LOAD(0); STORE(0); __syncthreads();
    for (int i = 0; i < 72; ++i) {
        if (i < 71) LOAD(i + 1);
        COMP(i & 1);
        if (i < 71) STORE((i + 1) & 1);
        __syncthreads();
    }

    const int g = lane >> 2, t2 = (lane & 3) * 2;
#pragma unroll
    for (int mt = 0; mt < 2; ++mt) {
        const int pr = pixbase + wm * 32 + mt * 16 + g;
#pragma unroll
        for (int nt = 0; nt < 2; ++nt) {
            const int oc = wn * 16 + nt * 8 + t2;
            if (oc < 18) {
                g_offs[pr * 18 + oc] = acc[mt][nt][0] + obs[oc];
                g_offs[(pr + 8) * 18 + oc] = acc[mt][nt][2] + obs[oc];
            }
            if (oc + 1 < 18) {
                g_offs[pr * 18 + oc + 1] = acc[mt][nt][1] + obs[oc + 1];
                g_offs[(pr + 8) * 18 + oc + 1] = acc[mt][nt][3] + obs[oc + 1];
            }
        }
    }
}

// ================= deformable conv + BN2 + residual + ReLU =================
#define DF_BUF 40960
#define DF_IB 81920
#define DF_CW 83968
#define DF_PK 102400
#define DF_SZ 107008

__global__ __launch_bounds__(256)
void deform_mma(const float* __restrict__ bg, const float* __restrict__ bb_,
                const float* __restrict__ bm, const float* __restrict__ bv,
                const float* __restrict__ resid, float* __restrict__ out) {
    extern __shared__ __align__(16) char S[];
    const int tid = threadIdx.x, lane = tid & 31, wid = tid >> 5;
    const int pixbase = blockIdx.x * 128, octile = blockIdx.y * 128;
    const u32 sb = smem_u32(S);
    float*  invbet = (float*)(S + DF_IB);
    float4* cwS = (float4*)(S + DF_CW);
    int*    cpkS = (int*)(S + DF_PK);
    {
        const float iv = bg[tid] * rsqrtf(bv[tid] + EPSBN);
        invbet[tid] = iv;
        invbet[256 + tid] = bb_[tid] - bm[tid] * iv;
    }
    for (int idx = tid; idx < 128 * 9; idx += 256) {
        const int p = idx / 9, k = idx - (idx / 9) * 9;
        const int gpq = pixbase + p;
        const int b = gpq / HWSZ, rm = gpq - b * HWSZ;
        const int yy = rm / WW, xx = rm - (rm / WW) * WW;
        const float oy = g_offs[gpq * 18 + k];
        const float ox = g_offs[gpq * 18 + 9 + k];
        const float ys = (float)(yy + k / 3 - 1) + oy;
        const float xs = (float)(xx + (k - (k / 3) * 3) - 1) + ox;
        const float yf = floorf(ys), xf = floorf(xs);
        const float ty = ys - yf, tx = xs - xf;
        const int iy0 = (int)yf, ix0 = (int)xf;
        const int iy1 = iy0 + 1, ix1 = ix0 + 1;
        const float vy0 = ((unsigned)iy0 < HH) ? 1.f : 0.f;
        const float vy1 = ((unsigned)iy1 < HH) ? 1.f : 0.f;
        const float vx0 = ((unsigned)ix0 < WW) ? 1.f : 0.f;
        const float vx1 = ((unsigned)ix1 < WW) ? 1.f : 0.f;
        cwS[idx] = make_float4((1.f - ty) * (1.f - tx) * vy0 * vx0,
                               (1.f - ty) * tx * vy0 * vx1,
                               ty * (1.f - tx) * vy1 * vx0,
                               ty * tx * vy1 * vx1);
        const int cy0 = min(max(iy0, 0), HH - 1), cy1 = min(max(iy1, 0), HH - 1);
        const int cx0 = min(max(ix0, 0), WW - 1), cx1 = min(max(ix1, 0), WW - 1);
        cpkS[idx] = cy0 | (cx0 << 8) | (cy1 << 16) | (cx1 << 24);
    }

    const int arow = tid >> 1, ah = tid & 1;
    const int gp = pixbase + arow;
    const int bIdx = gp / HWSZ;
    const int pixrowbase = bIdx * HWSZ;
    const u32 so = (u32)(arow * PADB + ah * 32);

    const int wm = wid >> 2, wn = wid & 3;
    float acc[4][4][4];
#pragma unroll
    for (int a = 0; a < 4; ++a)
#pragma unroll
        for (int b = 0; b < 4; ++b)
#pragma unroll
            for (int c = 0; c < 4; ++c) acc[a][b][c] = 0.f;

    uint4 pAh[2], pAl[2], pBh[2], pBl[2];

    auto LOAD = [&](int i) {
        const int k = i >> 3, c0 = (i & 7) << 5, cc = c0 + ah * 16;
        const float4 w = cwS[arow * 9 + k];
        const int pk = cpkS[arow * 9 + k];
        const int r00 = ((pixrowbase + (pk & 255) * WW + ((pk >> 8) & 255)) << 8) + cc;
        const int r01 = ((pixrowbase + (pk & 255) * WW + ((pk >> 24) & 255)) << 8) + cc;
        const int r10 = ((pixrowbase + ((pk >> 16) & 255) * WW + ((pk >> 8) & 255)) << 8) + cc;
        const int r11 = ((pixrowbase + ((pk >> 16) & 255) * WW + ((pk >> 24) & 255)) << 8) + cc;
        __align__(16) __nv_bfloat16 hh[16], ll[16];
#pragma unroll
        for (int gq = 0; gq < 4; ++gq) {
            const float4 s00 = *(const float4*)(g_out1f + r00 + gq * 4);
            const float4 s01 = *(const float4*)(g_out1f + r01 + gq * 4);
            const float4 s10 = *(const float4*)(g_out1f + r10 + gq * 4);
            const float4 s11 = *(const float4*)(g_out1f + r11 + gq * 4);
            float4 v;
            v.x = fmaf(w.x, s00.x, fmaf(w.y, s01.x, fmaf(w.z, s10.x, w.w * s11.x)));
            v.y = fmaf(w.x, s00.y, fmaf(w.y, s01.y, fmaf(w.z, s10.y, w.w * s11.y)));
            v.z = fmaf(w.x, s00.z, fmaf(w.y, s01.z, fmaf(w.z, s10.z, w.w * s11.z)));
            v.w = fmaf(w.x, s00.w, fmaf(w.y, s01.w, fmaf(w.z, s10.w, w.w * s11.w)));
            split_bf16(v.x, hh[gq * 4 + 0], ll[gq * 4 + 0]);
            split_bf16(v.y, hh[gq * 4 + 1], ll[gq * 4 + 1]);
            split_bf16(v.z, hh[gq * 4 + 2], ll[gq * 4 + 2]);
            split_bf16(v.w, hh[gq * 4 + 3], ll[gq * 4 + 3]);
        }
        pAh[0] = ((uint4*)hh)[0]; pAh[1] = ((uint4*)hh)[1];
        pAl[0] = ((uint4*)ll)[0]; pAl[1] = ((uint4*)ll)[1];
        const int wb = ((k * CH + octile + arow) << 8) + cc;
        pBh[0] = *(const uint4*)(g_w2h + wb); pBh[1] = *(const uint4*)(g_w2h + wb + 8);
        pBl[0] = *(const uint4*)(g_w2l + wb); pBl[1] = *(const uint4*)(g_w2l + wb + 8);
    };
    auto STORE = [&](int buf) {
        char* B0 = S + buf * DF_BUF;
        *(uint4*)(B0 + C1_AH + so) = pAh[0]; *(uint4*)(B0 + C1_AH + so + 16) = pAh[1];
        *(uint4*)(B0 + C1_AL + so) = pAl[0]; *(uint4*)(B0 + C1_AL + so + 16) = pAl[1];
        *(uint4*)(B0 + C1_BH + so) = pBh[0]; *(uint4*)(B0 + C1_BH + so + 16) = pBh[1];
        *(uint4*)(B0 + C1_BL + so) = pBl[0]; *(uint4*)(B0 + C1_BL + so + 16) = pBl[1];
    };

    const u32 aab = sb + (u32)((wm * 64 + (lane & 15)) * PADB + (lane >> 4) * 16);
    const u32 bab = sb + C1_BH +
        (u32)((wn * 32 + ((lane >> 4) << 3) + (lane & 7)) * PADB + ((lane >> 3) & 1) * 16);

    auto COMP = [&](int buf) {
        const u32 ab = aab + buf * DF_BUF, bbx = bab + buf * DF_BUF;
#pragma unroll
        for (int s = 0; s < 2; ++s) {
            const u32 ko = s * 32;
            u32 bh0[4], bh1[4], bl0[4], bl1[4];
            ldm4(bbx + ko, bh0);
            ldm4(bbx + 16 * PADB + ko, bh1);
            ldm4(bbx + (C1_BL - C1_BH) + ko, bl0);
            ldm4(bbx + (C1_BL - C1_BH) + 16 * PADB + ko, bl1);
            u32 ahf[4][4], alf[4][4];
#pragma unroll
            for (int mt = 0; mt < 4; ++mt) {
                ldm4(ab + mt * 16 * PADB + ko, ahf[mt]);
                ldm4(ab + (C1_AL - C1_AH) + mt * 16 * PADB + ko, alf[mt]);
            }
#pragma unroll
            for (int mt = 0; mt < 4; ++mt)
#pragma unroll
                for (int nt = 0; nt < 4; ++nt) {
                    u32* bhq = (nt < 2) ? bh0 : bh1;
                    u32* blq = (nt < 2) ? bl0 : bl1;
                    const int h = (nt & 1) * 2;
                    mma_bf16(acc[mt][nt], ahf[mt], bhq[h], bhq[h + 1]);
                    mma_bf16(acc[mt][nt], ahf[mt], blq[h], blq[h + 1]);
                    mma_bf16(acc[mt][nt], alf[mt], bhq[h], bhq[h + 1]);
                }
        }
    };

    __syncthreads();           // cw/cpk + invbet ready
    LOAD(0); STORE(0); __syncthreads();
    for (int i = 0; i < 72; ++i) {
        if (i < 71) LOAD(i + 1);
        COMP(i & 1);
        if (i < 71) STORE((i + 1) & 1);
        __syncthreads();
    }

    const int g = lane >> 2, t2 = (lane & 3) * 2;
#pragma unroll
    for (int mt = 0; mt < 4; ++mt) {
        const int pr0 = pixbase + wm * 64 + mt * 16 + g;
        const int pr1 = pr0 + 8;
        const int b0 = pr0 / HWSZ, rm0 = pr0 - b0 * HWSZ;
        const int b1 = pr1 / HWSZ, rm1 = pr1 - b1 * HWSZ;
        const int base0 = b0 * (CH * HWSZ) + rm0;
        const int base1 = b1 * (CH * HWSZ) + rm1;
#pragma unroll
        for (int nt = 0; nt < 4; ++nt) {
            const int oc = octile + wn * 32 + nt * 8 + t2;
            const float i0 = invbet[oc], i1 = invbet[oc + 1];
            const float e0 = invbet[256 + oc], e1 = invbet[256 + oc + 1];
            const int a00 = base0 + oc * HWSZ, a01 = a00 + HWSZ;
            const int a10 = base1 + oc * HWSZ, a11 = a10 + HWSZ;
            out[a00] = fmaxf(fmaf(acc[mt][nt][0], i0, e0) + resid[a00], 0.f);
            out[a01] = fmaxf(fmaf(acc[mt][nt][1], i1, e1) + resid[a01], 0.f);
            out[a10] = fmaxf(fmaf(acc[mt][nt][2], i0, e0) + resid[a10], 0.f);
            out[a11] = fmaxf(fmaf(acc[mt][nt][3], i1, e1) + resid[a11], 0.f);
        }
    }
}

// ---------------- launch ----------------
extern "C" void kernel_launch(void* const* d_in, const int* in_sizes, int n_in,
                              void* d_out, int out_size) {
    const float* x    = (const float*)d_in[0];
    const float* w1   = (const float*)d_in[1];
    const float* bn1g = (const float*)d_in[2];
    const float* bn1b = (const float*)d_in[3];
    const float* bn1m = (const float*)d_in[4];
    const float* bn1v = (const float*)d_in[5];
    const float* woff = (const float*)d_in[6];
    const float* offb = (const float*)d_in[7];
    const float* w2   = (const float*)d_in[8];
    const float* bn2g = (const float*)d_in[9];
    const float* bn2b = (const float*)d_in[10];
    const float* bn2m = (const float*)d_in[11];
    const float* bn2v = (const float*)d_in[12];
    float* out = (float*)d_out;

    static bool attr_done = false;
    if (!attr_done) {
        cudaFuncSetAttribute(conv1_mma,   cudaFuncAttributeMaxDynamicSharedMemorySize, C1_SZ);
        cudaFuncSetAttribute(convoff_mma, cudaFuncAttributeMaxDynamicSharedMemorySize, OF_SZ);
        cudaFuncSetAttribute(deform_mma,  cudaFuncAttributeMaxDynamicSharedMemorySize, DF_SZ);
        attr_done = true;
    }

    prep_x<<<dim3(98, 8, BATCH), dim3(32, 8)>>>(x);
    prep_w<<<2304, 256>>>(w1, 0);
    prep_w<<<2304, 256>>>(w2, 1);
    prep_woff<<<288, 256>>>(woff);
    conv1_mma<<<dim3(196, 2), 256, C1_SZ>>>(bn1g, bn1b, bn1m, bn1v);
    convoff_mma<<<196, 256, OF_SZ>>>(offb);
    deform_mma<<<dim3(196, 2), 256, DF_SZ>>>(bn2g, bn2b, bn2m, bn2v, x, out);
}